// round 12
// baseline (speedup 1.0000x reference)
#include <cuda_runtime.h>

// 2-layer LSTM (H=100, B=512, L=168) + fc head, 48-step autoregressive rollout.
// LAYER-PIPELINED: group L0 (threads 0..415) computes layer0 at time u while
// group L1 (threads 416..831) computes layer1 at time u-1 (independent:
// L0(u) needs h0(u-1); L1(u-1) needs h0(u-1), h1(u-2)).
// 128 CTAs x 4 batch elems; fma.rn.f32x2 on k-pairs (pure fp32 math).
//
// Weight QUADS g_WQ[q][r] = w[4q..4q+3][r], k-major concat:
//   quads 0..24  = W_hh0 (layer0)        k 0..99
//   quads 25..49 = W_ih1 (layer1 <- h0)  k 100..199
//   quads 50..74 = W_hh1 (layer1 <- h1)  k 200..299
// Quads 0..31 resident in smem (204.8 KB); 32..74 streamed from L2 with
// explicit rotating register prefetch (depth 3 in L0 group, depth 6 in L1).
// Group L0: gates0 = quads 0..24 ; gates1 partial = quads 25..31 (res) + 32..37
// Group L1: gates1 partial = quads 38..74 (37 streamed)
// gates1 = partialA + partialB, reduced in the cell-1 phase.
//
// hT[jp][b][2]: jp 0..49 = h0 pairs, jp 50..99 = h1 pairs. Quad q (q>=25)
// reads h entries sHu[4q-100 .. 4q-97]; quad q<25 reads sHu[4q .. 4q+3].

#define HH        100
#define R4        400
#define SEQ       168
#define STEPS     48
#define NBC       4
#define NCTA      128
#define NTHREADS  832
#define GRP1      416
#define NQRES     32
#define NQUADS    75

__device__ float4 g_WQ[NQUADS * R4];
__device__ float  g_b0[R4], g_b1[R4], g_wx0[R4];
__device__ float  g_fc[HH + 1];

// ---------------------------------------------------------------- prep ----
__device__ __forceinline__ float wt_val(int k, int r,
                                        const float* Whh0, const float* Wih1,
                                        const float* Whh1)
{
    if (k < 100)      return Whh0[r * HH + k];
    else if (k < 200) return Wih1[r * HH + (k - 100)];
    else              return Whh1[r * HH + (k - 200)];
}

__global__ void prep_kernel(const float* __restrict__ Wih0,
                            const float* __restrict__ Whh0,
                            const float* __restrict__ bih0,
                            const float* __restrict__ bhh0,
                            const float* __restrict__ Wih1,
                            const float* __restrict__ Whh1,
                            const float* __restrict__ bih1,
                            const float* __restrict__ bhh1,
                            const float* __restrict__ fcw,
                            const float* __restrict__ fcb)
{
    int i0 = blockIdx.x * blockDim.x + threadIdx.x;
    int stride = gridDim.x * blockDim.x;
    for (int idx = i0; idx < NQUADS * R4; idx += stride) {
        int q = idx / R4, r = idx - q * R4;
        g_WQ[idx] = make_float4(wt_val(4*q,   r, Whh0, Wih1, Whh1),
                                wt_val(4*q+1, r, Whh0, Wih1, Whh1),
                                wt_val(4*q+2, r, Whh0, Wih1, Whh1),
                                wt_val(4*q+3, r, Whh0, Wih1, Whh1));
    }
    for (int r = i0; r < R4; r += stride) {
        g_b0[r]  = bih0[r] + bhh0[r];
        g_b1[r]  = bih1[r] + bhh1[r];
        g_wx0[r] = Wih0[r];           // IN == 1
    }
    if (i0 < HH)  g_fc[i0] = fcw[i0];
    if (i0 == HH) g_fc[HH] = fcb[0];
}

// ---------------------------------------------------------------- math ----
typedef unsigned long long u64;

__device__ __forceinline__ void ffma2(u64& acc, u64 w, u64 h) {
    asm("fma.rn.f32x2 %0, %1, %2, %0;" : "+l"(acc) : "l"(w), "l"(h));
}
__device__ __forceinline__ float hsum2(u64 v) {
    float lo, hi;
    asm("mov.b64 {%0, %1}, %2;" : "=f"(lo), "=f"(hi) : "l"(v));
    return lo + hi;
}
__device__ __forceinline__ float sigf(float v) {
    return 1.f / (1.f + __expf(-v));
}
__device__ __forceinline__ float tanhfast(float v) {
    return __fdividef(2.f, 1.f + __expf(-2.f * v)) - 1.f;
}

// one quad: 2 pair-weights (w.x = pair 2q, w.y = pair 2q+1), h entry base hb
#define QUAD(wv, hb)                                                      \
    do {                                                                  \
        ulonglong2 hA0 = sHu[(hb)];     ulonglong2 hB0 = sHu[(hb) + 1];   \
        ulonglong2 hA1 = sHu[(hb) + 2]; ulonglong2 hB1 = sHu[(hb) + 3];   \
        ffma2(c0, (wv).x, hA0.x); ffma2(c1, (wv).x, hA0.y);               \
        ffma2(c2, (wv).x, hB0.x); ffma2(c3, (wv).x, hB0.y);               \
        ffma2(c0, (wv).y, hA1.x); ffma2(c1, (wv).y, hA1.y);               \
        ffma2(c2, (wv).y, hB1.x); ffma2(c3, (wv).y, hB1.y);               \
    } while (0)

// smem layout (float offsets)
#define SM_WQ   0                              // 32*400*4 = 51200
#define SM_HT   (NQRES * R4 * 4)               // 800 (100 jp * 8)
#define SM_G0   (SM_HT + 800)                  // 1600
#define SM_G1A  (SM_G0 + 1600)                 // 1600
#define SM_G1B  (SM_G1A + 1600)                // 1600
#define SM_C0   (SM_G1B + 1600)                // 400
#define SM_C1   (SM_C0 + R4)                   // 400
#define SM_FC   (SM_C1 + R4)                   // 104
#define SM_XT   (SM_FC + 104)                  // 4
#define SM_Y    (SM_XT + 4)                    // 4
#define SM_TOT  (SM_Y + 4)                     // 57712 f = 230848 B

__global__ void __launch_bounds__(NTHREADS, 1)
lstm_kernel(const float* __restrict__ x, float* __restrict__ out)
{
    extern __shared__ float sm[];
    ulonglong2* sWQ = (ulonglong2*)sm;             // quad view: [q*400 + r]
    float*      sHf = sm + SM_HT;
    ulonglong2* sHu = (ulonglong2*)(sm + SM_HT);   // [2*jp + bpair]
    float*      sG0 = sm + SM_G0;
    float*      sG1A = sm + SM_G1A;
    float*      sG1B = sm + SM_G1B;
    float*      sC0 = sm + SM_C0;
    float*      sC1 = sm + SM_C1;
    float*      sFC = sm + SM_FC;
    float*      sXt = sm + SM_XT;
    float*      sY  = sm + SM_Y;

    const int tid  = threadIdx.x;                  // 0..831
    const int gl1  = tid >= GRP1;
    const int r    = gl1 ? tid - GRP1 : tid;
    const bool act = r < R4;
    const bool aL0 = !gl1 && act;
    const bool aL1 =  gl1 && act;
    const int bb   = blockIdx.x * NBC;

    // resident quads (coalesced), zero state, fc copy
    {
        const float4* src = g_WQ;
        float4*       dst = (float4*)sm;
        for (int i = tid; i < NQRES * R4; i += NTHREADS) dst[i] = src[i];
    }
    for (int i = tid; i < 800; i += NTHREADS) sHf[i] = 0.f;
    for (int i = tid; i < R4; i += NTHREADS) { sC0[i] = 0.f; sC1[i] = 0.f; }
    for (int i = tid; i < HH + 1; i += NTHREADS) sFC[i] = g_fc[i];
    if (tid < NBC) sXt[tid] = x[(bb + tid) * SEQ];

    const int   rr   = act ? r : 0;
    const float wx0  = g_wx0[rr];
    const float b0r  = g_b0[rr];
    const float b1r  = g_b1[rr];
    const int   jb_b = rr / HH;
    const int   jb_j = rr - jb_b * HH;
    const int   hoff = (jb_j >> 1) * 8 + jb_b * 2 + (jb_j & 1);

    // weight bases
    const ulonglong2* w00 = sWQ + rr;                                // 0..24
    const ulonglong2* w1r = sWQ + 25 * R4 + rr;                      // 25..31
    const ulonglong2* w1sA = (const ulonglong2*)g_WQ + 32 * R4 + rr; // 32..37
    const ulonglong2* w1sB = (const ulonglong2*)g_WQ + 38 * R4 + rr; // 38..74

    __syncthreads();

    for (int s = 0; s < STEPS; s++) {
        for (int u = 0; u <= SEQ; u++) {
            // ===================== phase 1: gates =====================
            if (aL0) {
                if (u < SEQ) {
                    // gates0(u): quads 0..24 over h0(u-1)
                    u64 c0, c1, c2, c3;
                    {
                        float4 xv4 = *(const float4*)sXt;
                        float i0 = fmaf(wx0, xv4.x, b0r);
                        float i1 = fmaf(wx0, xv4.y, b0r);
                        float i2 = fmaf(wx0, xv4.z, b0r);
                        float i3 = fmaf(wx0, xv4.w, b0r);
                        asm("mov.b64 %0, {%1, %2};" : "=l"(c0) : "f"(i0), "f"(0.f));
                        asm("mov.b64 %0, {%1, %2};" : "=l"(c1) : "f"(i1), "f"(0.f));
                        asm("mov.b64 %0, {%1, %2};" : "=l"(c2) : "f"(i2), "f"(0.f));
                        asm("mov.b64 %0, {%1, %2};" : "=l"(c3) : "f"(i3), "f"(0.f));
                    }
                    #pragma unroll 5
                    for (int q = 0; q < 25; q++) {
                        ulonglong2 w = w00[q * R4];
                        QUAD(w, 4 * q);
                    }
                    ((float4*)sG0)[r] = make_float4(hsum2(c0), hsum2(c1),
                                                    hsum2(c2), hsum2(c3));
                }
                if (u >= 1) {
                    // partial gates1(u-1): quads 25..37 (h0 entries 0..51)
                    u64 c0 = 0, c1 = 0, c2 = 0, c3 = 0;
                    ulonglong2 buf[3];
                    #pragma unroll
                    for (int d = 0; d < 3; d++)            // prefetch streamed
                        buf[d] = __ldg(w1sA + d * R4);
                    #pragma unroll
                    for (int q = 0; q < 7; q++) {          // resident 25..31
                        ulonglong2 w = w1r[q * R4];
                        QUAD(w, 4 * q);
                    }
                    #pragma unroll
                    for (int i = 0; i < 6; i++) {          // streamed 32..37
                        ulonglong2 w = buf[i % 3];
                        if (i + 3 < 6) buf[i % 3] = __ldg(w1sA + (i + 3) * R4);
                        QUAD(w, 28 + 4 * i);
                    }
                    ((float4*)sG1A)[r] = make_float4(hsum2(c0), hsum2(c1),
                                                     hsum2(c2), hsum2(c3));
                }
            }
            if (aL1 && u >= 1) {
                // partial gates1(u-1): quads 38..74 (h entries 52..199)
                u64 c0 = 0, c1 = 0, c2 = 0, c3 = 0;
                ulonglong2 buf[6];
                #pragma unroll
                for (int d = 0; d < 6; d++)
                    buf[d] = __ldg(w1sB + d * R4);
                #pragma unroll 6
                for (int i = 0; i < 36; i++) {
                    ulonglong2 w = buf[i % 6];
                    if (i + 6 < 37) buf[i % 6] = __ldg(w1sB + (i + 6) * R4);
                    QUAD(w, 52 + 4 * i);
                }
                {
                    ulonglong2 w = buf[36 % 6];
                    QUAD(w, 52 + 4 * 36);
                }
                ((float4*)sG1B)[r] = make_float4(b1r + hsum2(c0), b1r + hsum2(c1),
                                                 b1r + hsum2(c2), b1r + hsum2(c3));
            }
            __syncthreads();

            // ===================== phase 2: cells =====================
            if (aL0 && u < SEQ) {
                int o = jb_j * 4 + jb_b;
                float gi = sG0[o];
                float gf = sG0[(jb_j + 100) * 4 + jb_b];
                float gg = sG0[(jb_j + 200) * 4 + jb_b];
                float go = sG0[(jb_j + 300) * 4 + jb_b];
                float c  = sC0[o];
                float cn = sigf(gf) * c + sigf(gi) * tanhfast(gg);
                float hn = sigf(go) * tanhfast(cn);
                sC0[o]    = cn;
                sHf[hoff] = hn;                        // h0(u)
            }
            if (aL1 && u >= 1) {
                int o = jb_j * 4 + jb_b;
                float gi = sG1A[o] + sG1B[o];
                float gf = sG1A[(jb_j+100)*4+jb_b] + sG1B[(jb_j+100)*4+jb_b];
                float gg = sG1A[(jb_j+200)*4+jb_b] + sG1B[(jb_j+200)*4+jb_b];
                float go = sG1A[(jb_j+300)*4+jb_b] + sG1B[(jb_j+300)*4+jb_b];
                float c  = sC1[o];
                float cn = sigf(gf) * c + sigf(gi) * tanhfast(gg);
                float hn = sigf(go) * tanhfast(cn);
                sC1[o]          = cn;
                sHf[400 + hoff] = hn;                  // h1(u-1)
            }
            if (tid >= GRP1 + 400 && tid < GRP1 + 404 && u < SEQ) {
                // prefetch x for next iteration (idle L1 lanes)
                int b = tid - (GRP1 + 400);
                float xv;
                if (u < SEQ - 1) {
                    int tt = u + 1;
                    if (s == 0)           xv = x[(bb + b) * SEQ + tt];
                    else if (tt < SEQ-1)  xv = x[(bb + b) * SEQ + tt + 1];
                    else                  xv = sY[b];   // y(s-1), stable
                } else {
                    // u == SEQ-1: first input of seq s+1 is x[1]
                    xv = x[(bb + b) * SEQ + 1];
                }
                sXt[b] = xv;
            }
            __syncthreads();
        }

        // ---- fc head: y(s) from h1(SEQ-1) (threads 0..127, L0 group) ----
        if (tid < 128) {
            int b = tid >> 5, l = tid & 31;
            float p = 0.f;
            for (int j = l; j < HH; j += 32)
                p += sHf[400 + (j >> 1) * 8 + b * 2 + (j & 1)] * sFC[j];
            #pragma unroll
            for (int off = 16; off; off >>= 1)
                p += __shfl_down_sync(0xffffffffu, p, off);
            if (l == 0) {
                float y = p + sFC[HH];
                sY[b] = y;                 // next read at u=SEQ-2 of seq s+1
                out[(bb + b) * STEPS + s] = y;
            }
        }
        // no sync needed: h1 next written at phase2 of u=1 (two syncs later);
        // fc threads rejoin at the phase-1 sync of u=0.
    }
}

// -------------------------------------------------------------- launch ----
extern "C" void kernel_launch(void* const* d_in, const int* in_sizes, int n_in,
                              void* d_out, int out_size)
{
    const float* x    = (const float*)d_in[0];
    const float* Wih0 = (const float*)d_in[1];
    const float* Whh0 = (const float*)d_in[2];
    const float* bih0 = (const float*)d_in[3];
    const float* bhh0 = (const float*)d_in[4];
    const float* Wih1 = (const float*)d_in[5];
    const float* Whh1 = (const float*)d_in[6];
    const float* bih1 = (const float*)d_in[7];
    const float* bhh1 = (const float*)d_in[8];
    const float* fcw  = (const float*)d_in[9];
    const float* fcb  = (const float*)d_in[10];
    float* out = (float*)d_out;

    cudaFuncSetAttribute(lstm_kernel,
                         cudaFuncAttributeMaxDynamicSharedMemorySize,
                         SM_TOT * (int)sizeof(float));

    prep_kernel<<<128, 256>>>(Wih0, Whh0, bih0, bhh0,
                              Wih1, Whh1, bih1, bhh1, fcw, fcb);
    lstm_kernel<<<NCTA, NTHREADS, SM_TOT * (int)sizeof(float)>>>(x, out);
}

// round 14
// speedup vs baseline: 1.0001x; 1.0001x over previous
#include <cuda_runtime.h>

// 2-layer LSTM (H=100, B=512, L=168) + fc head, 48-step autoregressive rollout.
// LAYER-PIPELINED: group L0 (threads 0..415) computes layer0 at time u while
// group L1 (threads 416..831) computes layer1 at time u-1 (independent:
// L0(u) needs h0(u-1); L1(u-1) needs h0(u-1), h1(u-2)).
// 128 CTAs x 4 batch elems; fma.rn.f32x2 on k-pairs (pure fp32 math).
//
// Weight QUADS g_WQ[q][r] = w[4q..4q+3][r], k-major concat:
//   quads 0..24  = W_hh0 (layer0)        k 0..99
//   quads 25..49 = W_ih1 (layer1 <- h0)  k 100..199
//   quads 50..74 = W_hh1 (layer1 <- h1)  k 200..299
// Quads 0..31 resident in smem (204.8 KB); 32..74 streamed from L2 with
// explicit rotating register prefetch (depth 3 in L0 group, depth 6 in L1).
// Group L0: gates0 = quads 0..24 ; gates1 partial = quads 25..31 (res) + 32..37
// Group L1: gates1 partial = quads 38..74 (37 streamed)
// gates1 = partialA + partialB, reduced in the cell-1 phase.
//
// hT[jp][b][2]: jp 0..49 = h0 pairs, jp 50..99 = h1 pairs. Quad q (q>=25)
// reads h entries sHu[4q-100 .. 4q-97]; quad q<25 reads sHu[4q .. 4q+3].

#define HH        100
#define R4        400
#define SEQ       168
#define STEPS     48
#define NBC       4
#define NCTA      128
#define NTHREADS  832
#define GRP1      416
#define NQRES     32
#define NQUADS    75

__device__ float4 g_WQ[NQUADS * R4];
__device__ float  g_b0[R4], g_b1[R4], g_wx0[R4];
__device__ float  g_fc[HH + 1];

// ---------------------------------------------------------------- prep ----
__device__ __forceinline__ float wt_val(int k, int r,
                                        const float* Whh0, const float* Wih1,
                                        const float* Whh1)
{
    if (k < 100)      return Whh0[r * HH + k];
    else if (k < 200) return Wih1[r * HH + (k - 100)];
    else              return Whh1[r * HH + (k - 200)];
}

__global__ void prep_kernel(const float* __restrict__ Wih0,
                            const float* __restrict__ Whh0,
                            const float* __restrict__ bih0,
                            const float* __restrict__ bhh0,
                            const float* __restrict__ Wih1,
                            const float* __restrict__ Whh1,
                            const float* __restrict__ bih1,
                            const float* __restrict__ bhh1,
                            const float* __restrict__ fcw,
                            const float* __restrict__ fcb)
{
    int i0 = blockIdx.x * blockDim.x + threadIdx.x;
    int stride = gridDim.x * blockDim.x;
    for (int idx = i0; idx < NQUADS * R4; idx += stride) {
        int q = idx / R4, r = idx - q * R4;
        g_WQ[idx] = make_float4(wt_val(4*q,   r, Whh0, Wih1, Whh1),
                                wt_val(4*q+1, r, Whh0, Wih1, Whh1),
                                wt_val(4*q+2, r, Whh0, Wih1, Whh1),
                                wt_val(4*q+3, r, Whh0, Wih1, Whh1));
    }
    for (int r = i0; r < R4; r += stride) {
        g_b0[r]  = bih0[r] + bhh0[r];
        g_b1[r]  = bih1[r] + bhh1[r];
        g_wx0[r] = Wih0[r];           // IN == 1
    }
    if (i0 < HH)  g_fc[i0] = fcw[i0];
    if (i0 == HH) g_fc[HH] = fcb[0];
}

// ---------------------------------------------------------------- math ----
typedef unsigned long long u64;

__device__ __forceinline__ void ffma2(u64& acc, u64 w, u64 h) {
    asm("fma.rn.f32x2 %0, %1, %2, %0;" : "+l"(acc) : "l"(w), "l"(h));
}
__device__ __forceinline__ float hsum2(u64 v) {
    float lo, hi;
    asm("mov.b64 {%0, %1}, %2;" : "=f"(lo), "=f"(hi) : "l"(v));
    return lo + hi;
}
__device__ __forceinline__ float sigf(float v) {
    return 1.f / (1.f + __expf(-v));
}
__device__ __forceinline__ float tanhfast(float v) {
    return __fdividef(2.f, 1.f + __expf(-2.f * v)) - 1.f;
}

// one quad: 2 pair-weights (w.x = pair 2q, w.y = pair 2q+1), h entry base hb
#define QUAD(wv, hb)                                                      \
    do {                                                                  \
        ulonglong2 hA0 = sHu[(hb)];     ulonglong2 hB0 = sHu[(hb) + 1];   \
        ulonglong2 hA1 = sHu[(hb) + 2]; ulonglong2 hB1 = sHu[(hb) + 3];   \
        ffma2(c0, (wv).x, hA0.x); ffma2(c1, (wv).x, hA0.y);               \
        ffma2(c2, (wv).x, hB0.x); ffma2(c3, (wv).x, hB0.y);               \
        ffma2(c0, (wv).y, hA1.x); ffma2(c1, (wv).y, hA1.y);               \
        ffma2(c2, (wv).y, hB1.x); ffma2(c3, (wv).y, hB1.y);               \
    } while (0)

// smem layout (float offsets)
#define SM_WQ   0                              // 32*400*4 = 51200
#define SM_HT   (NQRES * R4 * 4)               // 800 (100 jp * 8)
#define SM_G0   (SM_HT + 800)                  // 1600
#define SM_G1A  (SM_G0 + 1600)                 // 1600
#define SM_G1B  (SM_G1A + 1600)                // 1600
#define SM_C0   (SM_G1B + 1600)                // 400
#define SM_C1   (SM_C0 + R4)                   // 400
#define SM_FC   (SM_C1 + R4)                   // 104
#define SM_XT   (SM_FC + 104)                  // 4
#define SM_Y    (SM_XT + 4)                    // 4
#define SM_TOT  (SM_Y + 4)                     // 57712 f = 230848 B

__global__ void __launch_bounds__(NTHREADS, 1)
lstm_kernel(const float* __restrict__ x, float* __restrict__ out)
{
    extern __shared__ float sm[];
    ulonglong2* sWQ = (ulonglong2*)sm;             // quad view: [q*400 + r]
    float*      sHf = sm + SM_HT;
    ulonglong2* sHu = (ulonglong2*)(sm + SM_HT);   // [2*jp + bpair]
    float*      sG0 = sm + SM_G0;
    float*      sG1A = sm + SM_G1A;
    float*      sG1B = sm + SM_G1B;
    float*      sC0 = sm + SM_C0;
    float*      sC1 = sm + SM_C1;
    float*      sFC = sm + SM_FC;
    float*      sXt = sm + SM_XT;
    float*      sY  = sm + SM_Y;

    const int tid  = threadIdx.x;                  // 0..831
    const int gl1  = tid >= GRP1;
    const int r    = gl1 ? tid - GRP1 : tid;
    const bool act = r < R4;
    const bool aL0 = !gl1 && act;
    const bool aL1 =  gl1 && act;
    const int bb   = blockIdx.x * NBC;

    // resident quads (coalesced), zero state, fc copy
    {
        const float4* src = g_WQ;
        float4*       dst = (float4*)sm;
        for (int i = tid; i < NQRES * R4; i += NTHREADS) dst[i] = src[i];
    }
    for (int i = tid; i < 800; i += NTHREADS) sHf[i] = 0.f;
    for (int i = tid; i < R4; i += NTHREADS) { sC0[i] = 0.f; sC1[i] = 0.f; }
    for (int i = tid; i < HH + 1; i += NTHREADS) sFC[i] = g_fc[i];
    if (tid < NBC) sXt[tid] = x[(bb + tid) * SEQ];

    const int   rr   = act ? r : 0;
    const float wx0  = g_wx0[rr];
    const float b0r  = g_b0[rr];
    const float b1r  = g_b1[rr];
    const int   jb_b = rr / HH;
    const int   jb_j = rr - jb_b * HH;
    const int   hoff = (jb_j >> 1) * 8 + jb_b * 2 + (jb_j & 1);

    // weight bases
    const ulonglong2* w00 = sWQ + rr;                                // 0..24
    const ulonglong2* w1r = sWQ + 25 * R4 + rr;                      // 25..31
    const ulonglong2* w1sA = (const ulonglong2*)g_WQ + 32 * R4 + rr; // 32..37
    const ulonglong2* w1sB = (const ulonglong2*)g_WQ + 38 * R4 + rr; // 38..74

    __syncthreads();

    for (int s = 0; s < STEPS; s++) {
        for (int u = 0; u <= SEQ; u++) {
            // ===================== phase 1: gates =====================
            if (aL0) {
                if (u < SEQ) {
                    // gates0(u): quads 0..24 over h0(u-1)
                    u64 c0, c1, c2, c3;
                    {
                        float4 xv4 = *(const float4*)sXt;
                        float i0 = fmaf(wx0, xv4.x, b0r);
                        float i1 = fmaf(wx0, xv4.y, b0r);
                        float i2 = fmaf(wx0, xv4.z, b0r);
                        float i3 = fmaf(wx0, xv4.w, b0r);
                        asm("mov.b64 %0, {%1, %2};" : "=l"(c0) : "f"(i0), "f"(0.f));
                        asm("mov.b64 %0, {%1, %2};" : "=l"(c1) : "f"(i1), "f"(0.f));
                        asm("mov.b64 %0, {%1, %2};" : "=l"(c2) : "f"(i2), "f"(0.f));
                        asm("mov.b64 %0, {%1, %2};" : "=l"(c3) : "f"(i3), "f"(0.f));
                    }
                    #pragma unroll 5
                    for (int q = 0; q < 25; q++) {
                        ulonglong2 w = w00[q * R4];
                        QUAD(w, 4 * q);
                    }
                    ((float4*)sG0)[r] = make_float4(hsum2(c0), hsum2(c1),
                                                    hsum2(c2), hsum2(c3));
                }
                if (u >= 1) {
                    // partial gates1(u-1): quads 25..37 (h0 entries 0..51)
                    u64 c0 = 0, c1 = 0, c2 = 0, c3 = 0;
                    ulonglong2 buf[3];
                    #pragma unroll
                    for (int d = 0; d < 3; d++)            // prefetch streamed
                        buf[d] = __ldg(w1sA + d * R4);
                    #pragma unroll
                    for (int q = 0; q < 7; q++) {          // resident 25..31
                        ulonglong2 w = w1r[q * R4];
                        QUAD(w, 4 * q);
                    }
                    #pragma unroll
                    for (int i = 0; i < 6; i++) {          // streamed 32..37
                        ulonglong2 w = buf[i % 3];
                        if (i + 3 < 6) buf[i % 3] = __ldg(w1sA + (i + 3) * R4);
                        QUAD(w, 28 + 4 * i);
                    }
                    ((float4*)sG1A)[r] = make_float4(hsum2(c0), hsum2(c1),
                                                     hsum2(c2), hsum2(c3));
                }
            }
            if (aL1 && u >= 1) {
                // partial gates1(u-1): quads 38..74 (h entries 52..199)
                u64 c0 = 0, c1 = 0, c2 = 0, c3 = 0;
                ulonglong2 buf[6];
                #pragma unroll
                for (int d = 0; d < 6; d++)
                    buf[d] = __ldg(w1sB + d * R4);
                #pragma unroll 6
                for (int i = 0; i < 36; i++) {
                    ulonglong2 w = buf[i % 6];
                    if (i + 6 < 37) buf[i % 6] = __ldg(w1sB + (i + 6) * R4);
                    QUAD(w, 52 + 4 * i);
                }
                {
                    ulonglong2 w = buf[36 % 6];
                    QUAD(w, 52 + 4 * 36);
                }
                ((float4*)sG1B)[r] = make_float4(b1r + hsum2(c0), b1r + hsum2(c1),
                                                 b1r + hsum2(c2), b1r + hsum2(c3));
            }
            __syncthreads();

            // ===================== phase 2: cells =====================
            if (aL0 && u < SEQ) {
                int o = jb_j * 4 + jb_b;
                float gi = sG0[o];
                float gf = sG0[(jb_j + 100) * 4 + jb_b];
                float gg = sG0[(jb_j + 200) * 4 + jb_b];
                float go = sG0[(jb_j + 300) * 4 + jb_b];
                float c  = sC0[o];
                float cn = sigf(gf) * c + sigf(gi) * tanhfast(gg);
                float hn = sigf(go) * tanhfast(cn);
                sC0[o]    = cn;
                sHf[hoff] = hn;                        // h0(u)
            }
            if (aL1 && u >= 1) {
                int o = jb_j * 4 + jb_b;
                float gi = sG1A[o] + sG1B[o];
                float gf = sG1A[(jb_j+100)*4+jb_b] + sG1B[(jb_j+100)*4+jb_b];
                float gg = sG1A[(jb_j+200)*4+jb_b] + sG1B[(jb_j+200)*4+jb_b];
                float go = sG1A[(jb_j+300)*4+jb_b] + sG1B[(jb_j+300)*4+jb_b];
                float c  = sC1[o];
                float cn = sigf(gf) * c + sigf(gi) * tanhfast(gg);
                float hn = sigf(go) * tanhfast(cn);
                sC1[o]          = cn;
                sHf[400 + hoff] = hn;                  // h1(u-1)
            }
            if (tid >= GRP1 + 400 && tid < GRP1 + 404 && u < SEQ) {
                // prefetch x for next iteration (idle L1 lanes)
                int b = tid - (GRP1 + 400);
                float xv;
                if (u < SEQ - 1) {
                    int tt = u + 1;
                    if (s == 0)           xv = x[(bb + b) * SEQ + tt];
                    else if (tt < SEQ-1)  xv = x[(bb + b) * SEQ + tt + 1];
                    else                  xv = sY[b];   // y(s-1), stable
                } else {
                    // u == SEQ-1: first input of seq s+1 is x[1]
                    xv = x[(bb + b) * SEQ + 1];
                }
                sXt[b] = xv;
            }
            __syncthreads();
        }

        // ---- fc head: y(s) from h1(SEQ-1) (threads 0..127, L0 group) ----
        if (tid < 128) {
            int b = tid >> 5, l = tid & 31;
            float p = 0.f;
            for (int j = l; j < HH; j += 32)
                p += sHf[400 + (j >> 1) * 8 + b * 2 + (j & 1)] * sFC[j];
            #pragma unroll
            for (int off = 16; off; off >>= 1)
                p += __shfl_down_sync(0xffffffffu, p, off);
            if (l == 0) {
                float y = p + sFC[HH];
                sY[b] = y;                 // next read at u=SEQ-2 of seq s+1
                out[(bb + b) * STEPS + s] = y;
            }
        }
        // no sync needed: h1 next written at phase2 of u=1 (two syncs later);
        // fc threads rejoin at the phase-1 sync of u=0.
    }
}

// -------------------------------------------------------------- launch ----
extern "C" void kernel_launch(void* const* d_in, const int* in_sizes, int n_in,
                              void* d_out, int out_size)
{
    const float* x    = (const float*)d_in[0];
    const float* Wih0 = (const float*)d_in[1];
    const float* Whh0 = (const float*)d_in[2];
    const float* bih0 = (const float*)d_in[3];
    const float* bhh0 = (const float*)d_in[4];
    const float* Wih1 = (const float*)d_in[5];
    const float* Whh1 = (const float*)d_in[6];
    const float* bih1 = (const float*)d_in[7];
    const float* bhh1 = (const float*)d_in[8];
    const float* fcw  = (const float*)d_in[9];
    const float* fcb  = (const float*)d_in[10];
    float* out = (float*)d_out;

    cudaFuncSetAttribute(lstm_kernel,
                         cudaFuncAttributeMaxDynamicSharedMemorySize,
                         SM_TOT * (int)sizeof(float));

    prep_kernel<<<128, 256>>>(Wih0, Whh0, bih0, bhh0,
                              Wih1, Whh1, bih1, bhh1, fcw, fcb);
    lstm_kernel<<<NCTA, NTHREADS, SM_TOT * (int)sizeof(float)>>>(x, out);
}

// round 17
// speedup vs baseline: 3.1175x; 3.1172x over previous
#include <cuda_runtime.h>
#include <cuda_fp16.h>
#include <cstdint>

// 2-layer LSTM (H=100,B=512,L=168)+fc, 48-step rollout — mma.sync tensor path.
// 64 clusters x 2 CTAs, 8 batch/cluster, 416 thr (13 warps).
// rank0 = layer0 (A=W_hh0 fp16, K=112), rank1 = layer1 (A=[W_ih1|pad|W_hh1], K=224).
// Layer lag: at iter v rank0 computes h0(v), rank1 computes h1(v-1). One
// cluster.sync per iter; B (h vectors, fp16 hi+lo) parity double-buffered,
// stored in mma fragment order; h0 peer-written via st.shared::cluster.
// Warp w owns cells 8w..8w+7; M-tile pair [i|f],[g|o] puts all 4 gates of a
// cell in one thread's accumulators (2 batches) -> cell math in registers.

#define HH    100
#define SEQ   168
#define STEPS 48
#define TOT   (SEQ*STEPS)
#define NT    416

// smem byte offsets
#define OA  0u          // A frags: 13w x 2mt x 14kt x 32ln x 16B = 186368
#define OB  186368u     // B frags: 2par x 14kt x 2hl x 32ln x 8B = 14336
#define OX  200704u     // Xs: 8*168 f32 = 5376
#define OPM 206080u     // fc partials 8 f
#define OSY 206112u     // y feedback 8 f
#define STOT 206144u

static __device__ __forceinline__ uint32_t s2u(const void* p){
    uint32_t a; asm("{ .reg .u64 t; cvta.to.shared.u64 t, %1; cvt.u32.u64 %0, t; }":"=r"(a):"l"(p)); return a; }
static __device__ __forceinline__ uint32_t crank(){
    uint32_t r; asm("mov.u32 %0, %%cluster_ctarank;":"=r"(r)); return r; }
static __device__ __forceinline__ void st16(uint32_t a, __half v){
    asm volatile("st.shared.b16 [%0], %1;" :: "r"(a), "h"(__half_as_ushort(v)) : "memory"); }
static __device__ __forceinline__ void stp16(uint32_t a, uint32_t rk, __half v){
    asm volatile("{\n\t.reg .b32 ra;\n\tmapa.shared::cluster.u32 ra, %0, %1;\n\t"
        "st.shared::cluster.b16 [ra], %2;\n\t}" :: "r"(a),"r"(rk),"h"(__half_as_ushort(v)) : "memory"); }
static __device__ __forceinline__ void stp32(uint32_t a, uint32_t rk, float v){
    asm volatile("{\n\t.reg .b32 ra;\n\tmapa.shared::cluster.u32 ra, %0, %1;\n\t"
        "st.shared::cluster.f32 [ra], %2;\n\t}" :: "r"(a),"r"(rk),"f"(v) : "memory"); }
#define CLS() do { asm volatile("barrier.cluster.arrive.aligned;" ::: "memory"); \
                   asm volatile("barrier.cluster.wait.aligned;"  ::: "memory"); } while (0)
#define LD4(r0,r1,r2,r3,a) asm volatile("ld.shared.v4.b32 {%0,%1,%2,%3}, [%4];" \
    : "=r"(r0),"=r"(r1),"=r"(r2),"=r"(r3) : "r"(a))
#define LD2(r0,r1,a) asm volatile("ld.shared.v2.b32 {%0,%1}, [%2];" \
    : "=r"(r0),"=r"(r1) : "r"(a))
#define MMA(c0,c1,c2,c3,a0,a1,a2,a3,b0,b1) asm volatile( \
    "mma.sync.aligned.m16n8k16.row.col.f32.f16.f16.f32 " \
    "{%0,%1,%2,%3},{%4,%5,%6,%7},{%8,%9},{%0,%1,%2,%3};" \
    : "+f"(c0),"+f"(c1),"+f"(c2),"+f"(c3) \
    : "r"(a0),"r"(a1),"r"(a2),"r"(a3),"r"(b0),"r"(b1))

static __device__ __forceinline__ float sigf(float v){ return 1.f/(1.f+__expf(-v)); }
static __device__ __forceinline__ float thf(float v){ return __fdividef(2.f,1.f+__expf(-2.f*v))-1.f; }

__global__ void __launch_bounds__(NT,1) __cluster_dims__(2,1,1)
lstm_mma(const float* __restrict__ x,
         const float* __restrict__ Wih0, const float* __restrict__ Whh0,
         const float* __restrict__ bih0, const float* __restrict__ bhh0,
         const float* __restrict__ Wih1, const float* __restrict__ Whh1,
         const float* __restrict__ bih1, const float* __restrict__ bhh1,
         const float* __restrict__ fcw,  const float* __restrict__ fcb,
         float* __restrict__ out)
{
    extern __shared__ char sm[];
    const uint32_t smb = s2u(sm);
    const int tid = threadIdx.x, wid = tid>>5, lane = tid&31;
    const uint32_t rank = crank();
    const int pb = (int)(blockIdx.x>>1)*8;

    float* Xs = (float*)(sm+OX);
    float* PM = (float*)(sm+OPM);
    float* SY = (float*)(sm+OSY);

    const int g   = lane>>2, tig = lane&3;
    const int cell = 8*wid + g;
    const bool valid = cell < HH;
    const int n0 = 2*tig;

    // ---------------- init ----------------
    for (uint32_t i = (uint32_t)tid*4; i < 14336u; i += NT*4)
        *(uint32_t*)(sm + OB + i) = 0u;
    if (rank == 0)
        for (int i = tid; i < 8*SEQ; i += NT)
            Xs[i] = x[(pb + i/SEQ)*SEQ + (i%SEQ)];
    if (tid < 8) { PM[tid] = 0.f; SY[tid] = 0.f; }

    // A fragment fill: half index i = (((w*2+mt)*14+kt)*32+ln)*8+q, byte = 2*i
    for (int i = tid; i < 13*2*14*32*8; i += NT) {
        int q = i&7, ln = (i>>3)&31, tile = i>>8;
        int kt = tile%14, wm = tile/14, mt = wm&1, w = wm>>1;
        int row = (ln>>2) + 8*((q>>1)&1);
        int col = 2*(ln&3) + (q&1) + 8*(q>>2);
        int gate = (mt?2:0) + (row>=8 ? 1 : 0);
        int cr = 8*w + (row&7);
        int k = kt*16 + col;
        float v = 0.f;
        if (cr < HH) {
            int rb = (gate*HH + cr)*HH;
            if (rank == 0) { if (k < HH) v = Whh0[rb + k]; }
            else { if (k < HH) v = Wih1[rb + k];
                   else if (k >= 112 && k < 112+HH) v = Whh1[rb + k - 112]; }
        }
        *(__half*)(sm + (uint32_t)i*2) = __float2half_rn(v);
    }

    // per-thread constants
    float wxi=0,wxf=0,wxg=0,wxo=0, bi=0,bfv=0,bgv=0,bo=0, fcr=0;
    if (valid) {
        if (rank == 0) {
            wxi=Wih0[cell]; wxf=Wih0[HH+cell]; wxg=Wih0[2*HH+cell]; wxo=Wih0[3*HH+cell];
            bi =bih0[cell]+bhh0[cell];       bfv=bih0[HH+cell]+bhh0[HH+cell];
            bgv=bih0[2*HH+cell]+bhh0[2*HH+cell]; bo=bih0[3*HH+cell]+bhh0[3*HH+cell];
        } else {
            bi =bih1[cell]+bhh1[cell];       bfv=bih1[HH+cell]+bhh1[HH+cell];
            bgv=bih1[2*HH+cell]+bhh1[2*HH+cell]; bo=bih1[3*HH+cell]+bhh1[3*HH+cell];
            fcr = fcw[cell];
        }
    }
    const float fcb0 = fcb[0];

    // B write geometry for this thread's h slot (k = cell or 112+cell)
    const int kB = (rank==0) ? cell : 112+cell;
    const int kt_w = kB>>4, kk = kB&15;
    const int tgw = (kk>>1)&3, slot = (kk&1) | ((kk>>3)<<1);

    const uint32_t aoff = smb + (uint32_t)(wid*28)*512u + (uint32_t)lane*16u;
    float cs0 = 0.f, cs1 = 0.f;
    const int nkt = (rank==0) ? 7 : 14;
    int t = 0, s = 0;

    for (int v = 0; v <= TOT+1; v++) {
        CLS();
        const int par = v & 1;
        const bool mact = (rank==0) ? (v < TOT) : (v >= 1 && v <= TOT);

        float i0=0,i1=0,i2=0,i3=0, o0=0,o1=0,o2=0,o3=0;  // acc [i|f], [g|o]
        if (mact) {
            uint32_t boff = smb + OB + (uint32_t)par*7168u + (uint32_t)lane*8u;
            #pragma unroll 7
            for (int kt = 0; kt < nkt; kt++) {
                uint32_t a0,a1,a2,a3, c0,c1,c2,c3, bh0,bh1, bl0,bl1;
                LD4(a0,a1,a2,a3, aoff + (uint32_t)kt*512u);            // mt0 [i|f]
                LD4(c0,c1,c2,c3, aoff + 7168u + (uint32_t)kt*512u);    // mt1 [g|o]
                LD2(bh0,bh1, boff + (uint32_t)kt*512u);                // B hi
                LD2(bl0,bl1, boff + (uint32_t)kt*512u + 256u);         // B lo
                MMA(i0,i1,i2,i3, a0,a1,a2,a3, bh0,bh1);
                MMA(i0,i1,i2,i3, a0,a1,a2,a3, bl0,bl1);
                MMA(o0,o1,o2,o3, c0,c1,c2,c3, bh0,bh1);
                MMA(o0,o1,o2,o3, c0,c1,c2,c3, bl0,bl1);
            }
        }

        // ---------------- epilogue ----------------
        if (mact && valid) {
            const int parw = par ^ 1;
            const uint32_t wb = smb + OB + (uint32_t)(parw*14 + kt_w)*512u
                              + (uint32_t)tgw*8u + (uint32_t)slot*2u;
            #pragma unroll
            for (int e = 0; e < 2; e++) {
                const int nb = n0 + e;
                float ai = e ? i1 : i0, af = e ? i3 : i2;
                float ag = e ? o1 : o0, ao = e ? o3 : o2;
                float cst = e ? cs1 : cs0;
                float gi_, gf_, gg_, go_;
                if (rank == 0) {
                    float xv;
                    if (s == 0)            xv = Xs[nb*SEQ + t];
                    else if (t < SEQ-1)    xv = Xs[nb*SEQ + t + 1];
                    else                   xv = SY[nb];
                    gi_ = ai + fmaf(wxi, xv, bi);
                    gf_ = af + fmaf(wxf, xv, bfv);
                    gg_ = ag + fmaf(wxg, xv, bgv);
                    go_ = ao + fmaf(wxo, xv, bo);
                } else {
                    gi_ = ai + bi; gf_ = af + bfv; gg_ = ag + bgv; go_ = ao + bo;
                }
                float cn = sigf(gf_)*cst + sigf(gi_)*thf(gg_);
                if (e) cs1 = cn; else cs0 = cn;
                float h = sigf(go_)*thf(cn);
                __half hh = __float2half_rn(h);
                __half hl = __float2half_rn(h - __half2float(hh));
                uint32_t aH = wb + (uint32_t)nb*32u;   // lane=4*nb+tgw -> +nb*32B
                st16(aH,        hh);
                st16(aH + 256u, hl);
                if (rank == 0) { stp16(aH, 1u, hh); stp16(aH + 256u, 1u, hl); }
                else if (t == 0) atomicAdd(&PM[nb], h * fcr);   // u=v-1 seq end
            }
        }
        // finalize y(s') at v = (s'+1)*SEQ + 1
        if (rank == 1 && t == 1 && v > SEQ && tid < 8) {
            float y = PM[tid] + fcb0;
            out[(pb + tid)*STEPS + (v-2)/SEQ] = y;
            stp32(smb + OSY + (uint32_t)tid*4u, 0u, y);   // -> rank0 SY
            PM[tid] = 0.f;
        }
        if (++t == SEQ) { t = 0; s++; }
    }
}

extern "C" void kernel_launch(void* const* d_in, const int* in_sizes, int n_in,
                              void* d_out, int out_size)
{
    cudaFuncSetAttribute(lstm_mma, cudaFuncAttributeMaxDynamicSharedMemorySize, STOT);
    lstm_mma<<<128, NT, STOT>>>(
        (const float*)d_in[0], (const float*)d_in[1], (const float*)d_in[2],
        (const float*)d_in[3], (const float*)d_in[4], (const float*)d_in[5],
        (const float*)d_in[6], (const float*)d_in[7], (const float*)d_in[8],
        (const float*)d_in[9], (const float*)d_in[10], (float*)d_out);
}